// round 10
// baseline (speedup 1.0000x reference)
#include <cuda_runtime.h>
#include <cstdint>
#include <cstddef>

// Problem constants
#define BB 4
#define SS 4096
#define HH 16
#define DD 64
#define GM 16384   // B*S
#define GN 1024    // H*D == OUT
#define GK 1024    // IN == H*D

// Intermediate buffers (allocation-free rule: device globals)
__device__ float g_xp[(size_t)GM * GN];  // input projection  [B,S,H*D]
__device__ float g_y [(size_t)GM * GN];  // scan outputs      [B,S,H*D]

// ---------------------------------------------------------------------------
// tf32 helpers
// ---------------------------------------------------------------------------
__device__ __forceinline__ uint32_t f2tf32(float f) {
    uint32_t u;
    asm("cvt.rna.tf32.f32 %0, %1;" : "=r"(u) : "f"(f));
    return u;
}

__device__ __forceinline__ void mma_tf32(float c[4], const uint32_t a[4], const uint32_t b[2]) {
    asm volatile(
        "mma.sync.aligned.m16n8k8.row.col.f32.tf32.tf32.f32 "
        "{%0,%1,%2,%3}, {%4,%5,%6,%7}, {%8,%9}, {%0,%1,%2,%3};"
        : "+f"(c[0]), "+f"(c[1]), "+f"(c[2]), "+f"(c[3])
        : "r"(a[0]), "r"(a[1]), "r"(a[2]), "r"(a[3]), "r"(b[0]), "r"(b[1]));
}

// ---------------------------------------------------------------------------
// GEMM: C[M,N] = A[M,K] * B[N,K]^T   (A row-major, B row-major over K)
// Block tile 128x128, K-tile 32, 256 threads, 8 warps in 4(M) x 2(N),
// warp tile 32(M) x 64(N).  tf32 tensor cores, fp32 accumulate.
// smem layout: rows of 32 floats (8 x float4), float4-slot XOR-swizzled by
// (row & 7)  -> conflict-free for both the staging stores and fragment loads.
// ---------------------------------------------------------------------------
__global__ __launch_bounds__(256) void gemm_tf32(
    const float* __restrict__ A, const float* __restrict__ B, float* __restrict__ C)
{
    __shared__ uint4 As4[128 * 8];
    __shared__ uint4 Bs4[128 * 8];

    const int tid  = threadIdx.x;
    const int warp = tid >> 5;
    const int lane = tid & 31;
    const int wm   = warp >> 1;      // 0..3
    const int wn   = warp & 1;       // 0..1
    const int g    = lane >> 2;      // group 0..7
    const int t4   = lane & 3;       // thread-in-group
    const int lr   = tid >> 3;       // staging row 0..31
    const int lc4  = tid & 7;        // staging float4 col 0..7
    const int bm   = blockIdx.y * 128;
    const int bn   = blockIdx.x * 128;

    const float4* Ag = reinterpret_cast<const float4*>(A) + (size_t)(bm + lr) * (GK / 4) + lc4;
    const float4* Bg = reinterpret_cast<const float4*>(B) + (size_t)(bn + lr) * (GK / 4) + lc4;
    const int sw = lc4 ^ (lr & 7);

    float acc[2][8][4];
#pragma unroll
    for (int mi = 0; mi < 2; ++mi)
#pragma unroll
        for (int ni = 0; ni < 8; ++ni)
#pragma unroll
            for (int r = 0; r < 4; ++r) acc[mi][ni][r] = 0.f;

    // prologue: stage K-tile 0
    float4 pa[4], pb[4];
#pragma unroll
    for (int i = 0; i < 4; ++i) {
        pa[i] = Ag[(size_t)i * 32 * (GK / 4)];
        pb[i] = Bg[(size_t)i * 32 * (GK / 4)];
    }

    const uint32_t* As = reinterpret_cast<const uint32_t*>(As4);
    const uint32_t* Bs = reinterpret_cast<const uint32_t*>(Bs4);
    const uint32_t* Abase = As + (wm * 32 + g) * 32 + t4;
    const uint32_t* Bbase = Bs + (wn * 64 + g) * 32 + t4;

    for (int kt = 0; kt < GK / 32; ++kt) {
        __syncthreads();   // previous compute finished reading smem
#pragma unroll
        for (int i = 0; i < 4; ++i) {
            As4[(lr + 32 * i) * 8 + sw] =
                make_uint4(f2tf32(pa[i].x), f2tf32(pa[i].y), f2tf32(pa[i].z), f2tf32(pa[i].w));
            Bs4[(lr + 32 * i) * 8 + sw] =
                make_uint4(f2tf32(pb[i].x), f2tf32(pb[i].y), f2tf32(pb[i].z), f2tf32(pb[i].w));
        }
        __syncthreads();   // smem tile ready

        if (kt + 1 < GK / 32) {        // prefetch next tile (overlaps compute)
#pragma unroll
            for (int i = 0; i < 4; ++i) {
                pa[i] = Ag[(size_t)(kt + 1) * 8 + (size_t)i * 32 * (GK / 4)];
                pb[i] = Bg[(size_t)(kt + 1) * 8 + (size_t)i * 32 * (GK / 4)];
            }
        }

#pragma unroll
        for (int j = 0; j < 4; ++j) {          // 4 k8-steps per K-tile
            const int x0 = ((2 * j) ^ g) * 4;  // swizzled scalar offset, first half
            uint32_t af[2][4];
#pragma unroll
            for (int mi = 0; mi < 2; ++mi) {
                const uint32_t* p = Abase + mi * 16 * 32;
                af[mi][0] = p[x0];
                af[mi][1] = p[8 * 32 + x0];
                af[mi][2] = p[x0 ^ 4];
                af[mi][3] = p[8 * 32 + (x0 ^ 4)];
            }
#pragma unroll
            for (int ni = 0; ni < 8; ++ni) {
                const uint32_t* p = Bbase + ni * 8 * 32;
                uint32_t bf[2] = { p[x0], p[x0 ^ 4] };
                mma_tf32(acc[0][ni], af[0], bf);
                mma_tf32(acc[1][ni], af[1], bf);
            }
        }
    }

    // epilogue: direct float2 stores
#pragma unroll
    for (int mi = 0; mi < 2; ++mi) {
        const int row = bm + wm * 32 + mi * 16 + g;
#pragma unroll
        for (int ni = 0; ni < 8; ++ni) {
            const int col = bn + wn * 64 + ni * 8 + t4 * 2;
            *reinterpret_cast<float2*>(C + (size_t)row * GN + col) =
                make_float2(acc[mi][ni][0], acc[mi][ni][1]);
            *reinterpret_cast<float2*>(C + (size_t)(row + 8) * GN + col) =
                make_float2(acc[mi][ni][2], acc[mi][ni][3]);
        }
    }
}

// ---------------------------------------------------------------------------
// Recurrent scan: one block per (b,h).  128 threads: thread t handles output
// element e = t>>1, k-half = t&1 (32 MACs each).  h state double-buffered in
// smem -> exactly ONE bar.sync per step.  shfl_xor(1) pairs the two halves.
// x prefetched 2 steps ahead in registers.
// ---------------------------------------------------------------------------
__global__ void __launch_bounds__(128) rnn_scan(
    const float* __restrict__ xp, const float* __restrict__ h0,
    const float* __restrict__ Wst, const float* __restrict__ bias,
    float* __restrict__ y)
{
    const int b    = blockIdx.x >> 4;
    const int h    = blockIdx.x & 15;
    const int t    = threadIdx.x;
    const int e    = t >> 1;
    const int half = t & 1;

    __shared__ __align__(16) float hs[2][64];

    // per-thread weight slice: W[h][e][half*32 .. half*32+31]
    float w[32];
    {
        const float4* wr = reinterpret_cast<const float4*>(
            Wst + ((size_t)(h * 64 + e)) * 64 + half * 32);
#pragma unroll
        for (int c = 0; c < 8; ++c) {
            float4 v = wr[c];
            w[4 * c + 0] = v.x; w[4 * c + 1] = v.y;
            w[4 * c + 2] = v.z; w[4 * c + 3] = v.w;
        }
    }
    const float be = bias[h * 64 + e];

    if (t < 64) hs[0][t] = h0[(size_t)(b * HH + h) * 64 + t];

    const float* xb = xp + (size_t)b * SS * 1024 + h * 64 + e;
    float*       yb = y  + (size_t)b * SS * 1024 + h * 64 + e;

    float xc = xb[0];
    float x1 = xb[1024];
    __syncthreads();

    int cur = 0;
    for (int s = 0; s < SS; ++s) {
        const float4* hv = reinterpret_cast<const float4*>(&hs[cur][half * 32]);
        float a0 = 0.f, a1 = 0.f, a2 = 0.f, a3 = 0.f;
#pragma unroll
        for (int c = 0; c < 8; ++c) {
            float4 q = hv[c];
            a0 = fmaf(w[4 * c + 0], q.x, a0);
            a1 = fmaf(w[4 * c + 1], q.y, a1);
            a2 = fmaf(w[4 * c + 2], q.z, a2);
            a3 = fmaf(w[4 * c + 3], q.w, a3);
        }
        float acc = (a0 + a1) + (a2 + a3);
        acc += __shfl_xor_sync(0xffffffffu, acc, 1);   // both halves get full sum

        const float hn = tanhf(acc + be + xc);

        float xn = 0.f;
        if (s + 2 < SS) xn = xb[(size_t)(s + 2) * 1024];   // distance-2 prefetch

        if (half) yb[(size_t)s * 1024] = hn;     // lane 1 streams output
        else      hs[cur ^ 1][e] = hn;           // lane 0 updates state buffer
        __syncthreads();
        cur ^= 1;
        xc = x1; x1 = xn;
    }
}

// ---------------------------------------------------------------------------
// Launch
// ---------------------------------------------------------------------------
extern "C" void kernel_launch(void* const* d_in, const int* in_sizes, int n_in,
                              void* d_out, int out_size)
{
    const float* x     = (const float*)d_in[0];  // [B,S,IN]
    const float* h0    = (const float*)d_in[1];  // [B,H,D]
    const float* w_in  = (const float*)d_in[2];  // [H*D, IN]
    const float* Wst   = (const float*)d_in[3];  // [H,D,D]
    const float* bias  = (const float*)d_in[4];  // [H,D]
    const float* w_out = (const float*)d_in[5];  // [OUT, H*D]
    float* out = (float*)d_out;                  // [B,S,OUT]

    float *xp = nullptr, *yy = nullptr;
    cudaGetSymbolAddress((void**)&xp, g_xp);
    cudaGetSymbolAddress((void**)&yy, g_y);

    dim3 grid(GN / 128, GM / 128);   // (8, 128)
    gemm_tf32<<<grid, 256>>>(x, w_in, xp);          // input projection
    rnn_scan<<<BB * HH, 128>>>(xp, h0, Wst, bias, yy);  // sequential recurrence
    gemm_tf32<<<grid, 256>>>(yy, w_out, out);       // output projection
}

// round 11
// speedup vs baseline: 1.2832x; 1.2832x over previous
#include <cuda_runtime.h>
#include <cstdint>
#include <cstddef>

// Problem constants
#define BB 4
#define SS 4096
#define HH 16
#define DD 64
#define GM 16384   // B*S
#define GN 1024    // H*D == OUT
#define GK 1024    // IN == H*D

// Intermediate buffers (allocation-free rule: device globals)
__device__ float g_xp[(size_t)GM * GN];  // input projection  [B,S,H*D]
__device__ float g_y [(size_t)GM * GN];  // scan outputs      [B,S,H*D]

// ---------------------------------------------------------------------------
// tf32 helpers
// ---------------------------------------------------------------------------
__device__ __forceinline__ uint32_t f2tf32(float f) {
    uint32_t u;
    asm("cvt.rna.tf32.f32 %0, %1;" : "=r"(u) : "f"(f));
    return u;
}

__device__ __forceinline__ void mma_tf32(float c[4], const uint32_t a[4], const uint32_t b[2]) {
    asm volatile(
        "mma.sync.aligned.m16n8k8.row.col.f32.tf32.tf32.f32 "
        "{%0,%1,%2,%3}, {%4,%5,%6,%7}, {%8,%9}, {%0,%1,%2,%3};"
        : "+f"(c[0]), "+f"(c[1]), "+f"(c[2]), "+f"(c[3])
        : "r"(a[0]), "r"(a[1]), "r"(a[2]), "r"(a[3]), "r"(b[0]), "r"(b[1]));
}

// ---------------------------------------------------------------------------
// GEMM: C[M,N] = A[M,K] * B[N,K]^T   (A row-major, B row-major over K)
// Block tile 128x128, K-tile 32, 256 threads, 8 warps in 4(M) x 2(N),
// warp tile 32(M) x 64(N).  tf32 tensor cores, fp32 accumulate.
// smem layout: rows of 32 floats (8 x float4), float4-slot XOR-swizzled by
// (row & 7)  -> conflict-free for both the staging stores and fragment loads.
// ---------------------------------------------------------------------------
__global__ __launch_bounds__(256) void gemm_tf32(
    const float* __restrict__ A, const float* __restrict__ B, float* __restrict__ C)
{
    __shared__ uint4 As4[128 * 8];
    __shared__ uint4 Bs4[128 * 8];

    const int tid  = threadIdx.x;
    const int warp = tid >> 5;
    const int lane = tid & 31;
    const int wm   = warp >> 1;      // 0..3
    const int wn   = warp & 1;       // 0..1
    const int g    = lane >> 2;      // group 0..7
    const int t4   = lane & 3;       // thread-in-group
    const int lr   = tid >> 3;       // staging row 0..31
    const int lc4  = tid & 7;        // staging float4 col 0..7
    const int bm   = blockIdx.y * 128;
    const int bn   = blockIdx.x * 128;

    const float4* Ag = reinterpret_cast<const float4*>(A) + (size_t)(bm + lr) * (GK / 4) + lc4;
    const float4* Bg = reinterpret_cast<const float4*>(B) + (size_t)(bn + lr) * (GK / 4) + lc4;
    const int sw = lc4 ^ (lr & 7);

    float acc[2][8][4];
#pragma unroll
    for (int mi = 0; mi < 2; ++mi)
#pragma unroll
        for (int ni = 0; ni < 8; ++ni)
#pragma unroll
            for (int r = 0; r < 4; ++r) acc[mi][ni][r] = 0.f;

    // prologue: stage K-tile 0
    float4 pa[4], pb[4];
#pragma unroll
    for (int i = 0; i < 4; ++i) {
        pa[i] = Ag[(size_t)i * 32 * (GK / 4)];
        pb[i] = Bg[(size_t)i * 32 * (GK / 4)];
    }

    const uint32_t* As = reinterpret_cast<const uint32_t*>(As4);
    const uint32_t* Bs = reinterpret_cast<const uint32_t*>(Bs4);
    const uint32_t* Abase = As + (wm * 32 + g) * 32 + t4;
    const uint32_t* Bbase = Bs + (wn * 64 + g) * 32 + t4;

    for (int kt = 0; kt < GK / 32; ++kt) {
        __syncthreads();   // previous compute finished reading smem
#pragma unroll
        for (int i = 0; i < 4; ++i) {
            As4[(lr + 32 * i) * 8 + sw] =
                make_uint4(f2tf32(pa[i].x), f2tf32(pa[i].y), f2tf32(pa[i].z), f2tf32(pa[i].w));
            Bs4[(lr + 32 * i) * 8 + sw] =
                make_uint4(f2tf32(pb[i].x), f2tf32(pb[i].y), f2tf32(pb[i].z), f2tf32(pb[i].w));
        }
        __syncthreads();   // smem tile ready

        if (kt + 1 < GK / 32) {        // prefetch next tile (overlaps compute)
#pragma unroll
            for (int i = 0; i < 4; ++i) {
                pa[i] = Ag[(size_t)(kt + 1) * 8 + (size_t)i * 32 * (GK / 4)];
                pb[i] = Bg[(size_t)(kt + 1) * 8 + (size_t)i * 32 * (GK / 4)];
            }
        }

#pragma unroll
        for (int j = 0; j < 4; ++j) {          // 4 k8-steps per K-tile
            const int x0 = ((2 * j) ^ g) * 4;  // swizzled scalar offset, first half
            uint32_t af[2][4];
#pragma unroll
            for (int mi = 0; mi < 2; ++mi) {
                const uint32_t* p = Abase + mi * 16 * 32;
                af[mi][0] = p[x0];
                af[mi][1] = p[8 * 32 + x0];
                af[mi][2] = p[x0 ^ 4];
                af[mi][3] = p[8 * 32 + (x0 ^ 4)];
            }
#pragma unroll
            for (int ni = 0; ni < 8; ++ni) {
                const uint32_t* p = Bbase + ni * 8 * 32;
                uint32_t bf[2] = { p[x0], p[x0 ^ 4] };
                mma_tf32(acc[0][ni], af[0], bf);
                mma_tf32(acc[1][ni], af[1], bf);
            }
        }
    }

    // epilogue: direct float2 stores
#pragma unroll
    for (int mi = 0; mi < 2; ++mi) {
        const int row = bm + wm * 32 + mi * 16 + g;
#pragma unroll
        for (int ni = 0; ni < 8; ++ni) {
            const int col = bn + wn * 64 + ni * 8 + t4 * 2;
            *reinterpret_cast<float2*>(C + (size_t)row * GN + col) =
                make_float2(acc[mi][ni][0], acc[mi][ni][1]);
            *reinterpret_cast<float2*>(C + (size_t)(row + 8) * GN + col) =
                make_float2(acc[mi][ni][2], acc[mi][ni][3]);
        }
    }
}

// ---------------------------------------------------------------------------
// Recurrent scan: one block per (b,h).  128 threads: thread t handles output
// element e = t>>1, k-half = t&1 (32 MACs each).  h state double-buffered in
// smem -> exactly ONE bar.sync per step.  shfl_xor(1) pairs the two halves.
// x prefetched 2 steps ahead in registers.
// ---------------------------------------------------------------------------
__global__ void __launch_bounds__(128) rnn_scan(
    const float* __restrict__ xp, const float* __restrict__ h0,
    const float* __restrict__ Wst, const float* __restrict__ bias,
    float* __restrict__ y)
{
    const int b    = blockIdx.x >> 4;
    const int h    = blockIdx.x & 15;
    const int t    = threadIdx.x;
    const int e    = t >> 1;
    const int half = t & 1;

    __shared__ __align__(16) float hs[2][64];

    // per-thread weight slice: W[h][e][half*32 .. half*32+31]
    float w[32];
    {
        const float4* wr = reinterpret_cast<const float4*>(
            Wst + ((size_t)(h * 64 + e)) * 64 + half * 32);
#pragma unroll
        for (int c = 0; c < 8; ++c) {
            float4 v = wr[c];
            w[4 * c + 0] = v.x; w[4 * c + 1] = v.y;
            w[4 * c + 2] = v.z; w[4 * c + 3] = v.w;
        }
    }
    const float be = bias[h * 64 + e];

    if (t < 64) hs[0][t] = h0[(size_t)(b * HH + h) * 64 + t];

    const float* xb = xp + (size_t)b * SS * 1024 + h * 64 + e;
    float*       yb = y  + (size_t)b * SS * 1024 + h * 64 + e;

    float xc = xb[0];
    float x1 = xb[1024];
    __syncthreads();

    int cur = 0;
    for (int s = 0; s < SS; ++s) {
        const float4* hv = reinterpret_cast<const float4*>(&hs[cur][half * 32]);
        float a0 = 0.f, a1 = 0.f, a2 = 0.f, a3 = 0.f;
#pragma unroll
        for (int c = 0; c < 8; ++c) {
            float4 q = hv[c];
            a0 = fmaf(w[4 * c + 0], q.x, a0);
            a1 = fmaf(w[4 * c + 1], q.y, a1);
            a2 = fmaf(w[4 * c + 2], q.z, a2);
            a3 = fmaf(w[4 * c + 3], q.w, a3);
        }
        float acc = (a0 + a1) + (a2 + a3);
        acc += __shfl_xor_sync(0xffffffffu, acc, 1);   // both halves get full sum

        const float hn = tanhf(acc + be + xc);

        float xn = 0.f;
        if (s + 2 < SS) xn = xb[(size_t)(s + 2) * 1024];   // distance-2 prefetch

        if (half) yb[(size_t)s * 1024] = hn;     // lane 1 streams output
        else      hs[cur ^ 1][e] = hn;           // lane 0 updates state buffer
        __syncthreads();
        cur ^= 1;
        xc = x1; x1 = xn;
    }
}

// ---------------------------------------------------------------------------
// Launch
// ---------------------------------------------------------------------------
extern "C" void kernel_launch(void* const* d_in, const int* in_sizes, int n_in,
                              void* d_out, int out_size)
{
    const float* x     = (const float*)d_in[0];  // [B,S,IN]
    const float* h0    = (const float*)d_in[1];  // [B,H,D]
    const float* w_in  = (const float*)d_in[2];  // [H*D, IN]
    const float* Wst   = (const float*)d_in[3];  // [H,D,D]
    const float* bias  = (const float*)d_in[4];  // [H,D]
    const float* w_out = (const float*)d_in[5];  // [OUT, H*D]
    float* out = (float*)d_out;                  // [B,S,OUT]

    float *xp = nullptr, *yy = nullptr;
    cudaGetSymbolAddress((void**)&xp, g_xp);
    cudaGetSymbolAddress((void**)&yy, g_y);

    dim3 grid(GN / 128, GM / 128);   // (8, 128)
    gemm_tf32<<<grid, 256>>>(x, w_in, xp);          // input projection
    rnn_scan<<<BB * HH, 128>>>(xp, h0, Wst, bias, yy);  // sequential recurrence
    gemm_tf32<<<grid, 256>>>(yy, w_out, out);       // output projection
}

// round 12
// speedup vs baseline: 1.2905x; 1.0057x over previous
#include <cuda_runtime.h>
#include <cstdint>
#include <cstddef>

// Problem constants
#define BB 4
#define SS 4096
#define HH 16
#define DD 64
#define GM 16384   // B*S
#define GN 1024    // H*D == OUT
#define GK 1024    // IN == H*D

// Intermediate buffers (allocation-free rule: device globals)
__device__ float g_xp[(size_t)GM * GN];  // input projection  [B,S,H*D]
__device__ float g_y [(size_t)GM * GN];  // scan outputs      [B,S,H*D]

// ---------------------------------------------------------------------------
// tf32 helpers
// ---------------------------------------------------------------------------
__device__ __forceinline__ uint32_t f2tf32(float f) {
    uint32_t u;
    asm("cvt.rna.tf32.f32 %0, %1;" : "=r"(u) : "f"(f));
    return u;
}

__device__ __forceinline__ void mma_tf32(float c[4], const uint32_t a[4], const uint32_t b[2]) {
    asm volatile(
        "mma.sync.aligned.m16n8k8.row.col.f32.tf32.tf32.f32 "
        "{%0,%1,%2,%3}, {%4,%5,%6,%7}, {%8,%9}, {%0,%1,%2,%3};"
        : "+f"(c[0]), "+f"(c[1]), "+f"(c[2]), "+f"(c[3])
        : "r"(a[0]), "r"(a[1]), "r"(a[2]), "r"(a[3]), "r"(b[0]), "r"(b[1]));
}

// ---------------------------------------------------------------------------
// GEMM: C[M,N] = A[M,K] * B[N,K]^T   (A row-major, B row-major over K)
// Block tile 128x128, K-tile 32, 256 threads, 8 warps in 4(M) x 2(N),
// warp tile 32(M) x 64(N).  tf32 tensor cores, fp32 accumulate.
// smem layout: rows of 32 floats (8 x float4), float4-slot XOR-swizzled by
// (row & 7)  -> conflict-free for both the staging stores and fragment loads.
// ---------------------------------------------------------------------------
__global__ __launch_bounds__(256) void gemm_tf32(
    const float* __restrict__ A, const float* __restrict__ B, float* __restrict__ C)
{
    __shared__ uint4 As4[128 * 8];
    __shared__ uint4 Bs4[128 * 8];

    const int tid  = threadIdx.x;
    const int warp = tid >> 5;
    const int lane = tid & 31;
    const int wm   = warp >> 1;      // 0..3
    const int wn   = warp & 1;       // 0..1
    const int g    = lane >> 2;      // group 0..7
    const int t4   = lane & 3;       // thread-in-group
    const int lr   = tid >> 3;       // staging row 0..31
    const int lc4  = tid & 7;        // staging float4 col 0..7
    const int bm   = blockIdx.y * 128;
    const int bn   = blockIdx.x * 128;

    const float4* Ag = reinterpret_cast<const float4*>(A) + (size_t)(bm + lr) * (GK / 4) + lc4;
    const float4* Bg = reinterpret_cast<const float4*>(B) + (size_t)(bn + lr) * (GK / 4) + lc4;
    const int sw = lc4 ^ (lr & 7);

    float acc[2][8][4];
#pragma unroll
    for (int mi = 0; mi < 2; ++mi)
#pragma unroll
        for (int ni = 0; ni < 8; ++ni)
#pragma unroll
            for (int r = 0; r < 4; ++r) acc[mi][ni][r] = 0.f;

    // prologue: stage K-tile 0
    float4 pa[4], pb[4];
#pragma unroll
    for (int i = 0; i < 4; ++i) {
        pa[i] = Ag[(size_t)i * 32 * (GK / 4)];
        pb[i] = Bg[(size_t)i * 32 * (GK / 4)];
    }

    const uint32_t* As = reinterpret_cast<const uint32_t*>(As4);
    const uint32_t* Bs = reinterpret_cast<const uint32_t*>(Bs4);
    const uint32_t* Abase = As + (wm * 32 + g) * 32 + t4;
    const uint32_t* Bbase = Bs + (wn * 64 + g) * 32 + t4;

    for (int kt = 0; kt < GK / 32; ++kt) {
        __syncthreads();   // previous compute finished reading smem
#pragma unroll
        for (int i = 0; i < 4; ++i) {
            As4[(lr + 32 * i) * 8 + sw] =
                make_uint4(f2tf32(pa[i].x), f2tf32(pa[i].y), f2tf32(pa[i].z), f2tf32(pa[i].w));
            Bs4[(lr + 32 * i) * 8 + sw] =
                make_uint4(f2tf32(pb[i].x), f2tf32(pb[i].y), f2tf32(pb[i].z), f2tf32(pb[i].w));
        }
        __syncthreads();   // smem tile ready

        if (kt + 1 < GK / 32) {        // prefetch next tile (overlaps compute)
#pragma unroll
            for (int i = 0; i < 4; ++i) {
                pa[i] = Ag[(size_t)(kt + 1) * 8 + (size_t)i * 32 * (GK / 4)];
                pb[i] = Bg[(size_t)(kt + 1) * 8 + (size_t)i * 32 * (GK / 4)];
            }
        }

#pragma unroll
        for (int j = 0; j < 4; ++j) {          // 4 k8-steps per K-tile
            const int x0 = ((2 * j) ^ g) * 4;  // swizzled scalar offset, first half
            uint32_t af[2][4];
#pragma unroll
            for (int mi = 0; mi < 2; ++mi) {
                const uint32_t* p = Abase + mi * 16 * 32;
                af[mi][0] = p[x0];
                af[mi][1] = p[8 * 32 + x0];
                af[mi][2] = p[x0 ^ 4];
                af[mi][3] = p[8 * 32 + (x0 ^ 4)];
            }
#pragma unroll
            for (int ni = 0; ni < 8; ++ni) {
                const uint32_t* p = Bbase + ni * 8 * 32;
                uint32_t bf[2] = { p[x0], p[x0 ^ 4] };
                mma_tf32(acc[0][ni], af[0], bf);
                mma_tf32(acc[1][ni], af[1], bf);
            }
        }
    }

    // epilogue: direct float2 stores
#pragma unroll
    for (int mi = 0; mi < 2; ++mi) {
        const int row = bm + wm * 32 + mi * 16 + g;
#pragma unroll
        for (int ni = 0; ni < 8; ++ni) {
            const int col = bn + wn * 64 + ni * 8 + t4 * 2;
            *reinterpret_cast<float2*>(C + (size_t)row * GN + col) =
                make_float2(acc[mi][ni][0], acc[mi][ni][1]);
            *reinterpret_cast<float2*>(C + (size_t)(row + 8) * GN + col) =
                make_float2(acc[mi][ni][2], acc[mi][ni][3]);
        }
    }
}

// ---------------------------------------------------------------------------
// Recurrent scan: one block per (b,h).  128 threads: thread t handles output
// element e = t>>1, k-half = t&1 (32 MACs each).  h state double-buffered in
// smem -> exactly ONE bar.sync per step.  shfl_xor(1) pairs the two halves.
// x prefetched 2 steps ahead in registers.
// ---------------------------------------------------------------------------
__global__ void __launch_bounds__(128) rnn_scan(
    const float* __restrict__ xp, const float* __restrict__ h0,
    const float* __restrict__ Wst, const float* __restrict__ bias,
    float* __restrict__ y)
{
    const int b    = blockIdx.x >> 4;
    const int h    = blockIdx.x & 15;
    const int t    = threadIdx.x;
    const int e    = t >> 1;
    const int half = t & 1;

    __shared__ __align__(16) float hs[2][64];

    // per-thread weight slice: W[h][e][half*32 .. half*32+31]
    float w[32];
    {
        const float4* wr = reinterpret_cast<const float4*>(
            Wst + ((size_t)(h * 64 + e)) * 64 + half * 32);
#pragma unroll
        for (int c = 0; c < 8; ++c) {
            float4 v = wr[c];
            w[4 * c + 0] = v.x; w[4 * c + 1] = v.y;
            w[4 * c + 2] = v.z; w[4 * c + 3] = v.w;
        }
    }
    const float be = bias[h * 64 + e];

    if (t < 64) hs[0][t] = h0[(size_t)(b * HH + h) * 64 + t];

    const float* xb = xp + (size_t)b * SS * 1024 + h * 64 + e;
    float*       yb = y  + (size_t)b * SS * 1024 + h * 64 + e;

    float xc = xb[0];
    float x1 = xb[1024];
    __syncthreads();

    int cur = 0;
    for (int s = 0; s < SS; ++s) {
        const float4* hv = reinterpret_cast<const float4*>(&hs[cur][half * 32]);
        float a0 = 0.f, a1 = 0.f, a2 = 0.f, a3 = 0.f;
#pragma unroll
        for (int c = 0; c < 8; ++c) {
            float4 q = hv[c];
            a0 = fmaf(w[4 * c + 0], q.x, a0);
            a1 = fmaf(w[4 * c + 1], q.y, a1);
            a2 = fmaf(w[4 * c + 2], q.z, a2);
            a3 = fmaf(w[4 * c + 3], q.w, a3);
        }
        float acc = (a0 + a1) + (a2 + a3);
        acc += __shfl_xor_sync(0xffffffffu, acc, 1);   // both halves get full sum

        const float hn = tanhf(acc + be + xc);

        float xn = 0.f;
        if (s + 2 < SS) xn = xb[(size_t)(s + 2) * 1024];   // distance-2 prefetch

        if (half) yb[(size_t)s * 1024] = hn;     // lane 1 streams output
        else      hs[cur ^ 1][e] = hn;           // lane 0 updates state buffer
        __syncthreads();
        cur ^= 1;
        xc = x1; x1 = xn;
    }
}

// ---------------------------------------------------------------------------
// Launch
// ---------------------------------------------------------------------------
extern "C" void kernel_launch(void* const* d_in, const int* in_sizes, int n_in,
                              void* d_out, int out_size)
{
    const float* x     = (const float*)d_in[0];  // [B,S,IN]
    const float* h0    = (const float*)d_in[1];  // [B,H,D]
    const float* w_in  = (const float*)d_in[2];  // [H*D, IN]
    const float* Wst   = (const float*)d_in[3];  // [H,D,D]
    const float* bias  = (const float*)d_in[4];  // [H,D]
    const float* w_out = (const float*)d_in[5];  // [OUT, H*D]
    float* out = (float*)d_out;                  // [B,S,OUT]

    float *xp = nullptr, *yy = nullptr;
    cudaGetSymbolAddress((void**)&xp, g_xp);
    cudaGetSymbolAddress((void**)&yy, g_y);

    dim3 grid(GN / 128, GM / 128);   // (8, 128)
    gemm_tf32<<<grid, 256>>>(x, w_in, xp);          // input projection
    rnn_scan<<<BB * HH, 128>>>(xp, h0, Wst, bias, yy);  // sequential recurrence
    gemm_tf32<<<grid, 256>>>(yy, w_out, out);       // output projection
}

// round 13
// speedup vs baseline: 2.1427x; 1.6603x over previous
#include <cuda_runtime.h>
#include <cstdint>
#include <cstddef>

// Problem constants
#define BB 4
#define SS 4096
#define HH 16
#define DD 64
#define GM 16384   // B*S
#define GN 1024    // H*D == OUT
#define GK 1024    // IN == H*D

// Intermediate buffers (allocation-free rule: device globals)
__device__ float g_xp[(size_t)GM * GN];  // input projection  [B,S,H*D]
__device__ float g_y [(size_t)GM * GN];  // scan outputs      [B,S,H*D]

// ---------------------------------------------------------------------------
// tf32 helpers
// ---------------------------------------------------------------------------
__device__ __forceinline__ uint32_t f2tf32(float f) {
    uint32_t u;
    asm("cvt.rna.tf32.f32 %0, %1;" : "=r"(u) : "f"(f));
    return u;
}

__device__ __forceinline__ void mma_tf32(float c[4], const uint32_t a[4], const uint32_t b[2]) {
    asm volatile(
        "mma.sync.aligned.m16n8k8.row.col.f32.tf32.tf32.f32 "
        "{%0,%1,%2,%3}, {%4,%5,%6,%7}, {%8,%9}, {%0,%1,%2,%3};"
        : "+f"(c[0]), "+f"(c[1]), "+f"(c[2]), "+f"(c[3])
        : "r"(a[0]), "r"(a[1]), "r"(a[2]), "r"(a[3]), "r"(b[0]), "r"(b[1]));
}

// ---------------------------------------------------------------------------
// GEMM: C[M,N] = A[M,K] * B[N,K]^T   (unchanged from R12 — 265us each)
// ---------------------------------------------------------------------------
__global__ __launch_bounds__(256) void gemm_tf32(
    const float* __restrict__ A, const float* __restrict__ B, float* __restrict__ C)
{
    __shared__ uint4 As4[128 * 8];
    __shared__ uint4 Bs4[128 * 8];

    const int tid  = threadIdx.x;
    const int warp = tid >> 5;
    const int lane = tid & 31;
    const int wm   = warp >> 1;      // 0..3
    const int wn   = warp & 1;       // 0..1
    const int g    = lane >> 2;      // group 0..7
    const int t4   = lane & 3;       // thread-in-group
    const int lr   = tid >> 3;       // staging row 0..31
    const int lc4  = tid & 7;        // staging float4 col 0..7
    const int bm   = blockIdx.y * 128;
    const int bn   = blockIdx.x * 128;

    const float4* Ag = reinterpret_cast<const float4*>(A) + (size_t)(bm + lr) * (GK / 4) + lc4;
    const float4* Bg = reinterpret_cast<const float4*>(B) + (size_t)(bn + lr) * (GK / 4) + lc4;
    const int sw = lc4 ^ (lr & 7);

    float acc[2][8][4];
#pragma unroll
    for (int mi = 0; mi < 2; ++mi)
#pragma unroll
        for (int ni = 0; ni < 8; ++ni)
#pragma unroll
            for (int r = 0; r < 4; ++r) acc[mi][ni][r] = 0.f;

    // prologue: stage K-tile 0
    float4 pa[4], pb[4];
#pragma unroll
    for (int i = 0; i < 4; ++i) {
        pa[i] = Ag[(size_t)i * 32 * (GK / 4)];
        pb[i] = Bg[(size_t)i * 32 * (GK / 4)];
    }

    const uint32_t* As = reinterpret_cast<const uint32_t*>(As4);
    const uint32_t* Bs = reinterpret_cast<const uint32_t*>(Bs4);
    const uint32_t* Abase = As + (wm * 32 + g) * 32 + t4;
    const uint32_t* Bbase = Bs + (wn * 64 + g) * 32 + t4;

    for (int kt = 0; kt < GK / 32; ++kt) {
        __syncthreads();   // previous compute finished reading smem
#pragma unroll
        for (int i = 0; i < 4; ++i) {
            As4[(lr + 32 * i) * 8 + sw] =
                make_uint4(f2tf32(pa[i].x), f2tf32(pa[i].y), f2tf32(pa[i].z), f2tf32(pa[i].w));
            Bs4[(lr + 32 * i) * 8 + sw] =
                make_uint4(f2tf32(pb[i].x), f2tf32(pb[i].y), f2tf32(pb[i].z), f2tf32(pb[i].w));
        }
        __syncthreads();   // smem tile ready

        if (kt + 1 < GK / 32) {        // prefetch next tile (overlaps compute)
#pragma unroll
            for (int i = 0; i < 4; ++i) {
                pa[i] = Ag[(size_t)(kt + 1) * 8 + (size_t)i * 32 * (GK / 4)];
                pb[i] = Bg[(size_t)(kt + 1) * 8 + (size_t)i * 32 * (GK / 4)];
            }
        }

#pragma unroll
        for (int j = 0; j < 4; ++j) {          // 4 k8-steps per K-tile
            const int x0 = ((2 * j) ^ g) * 4;  // swizzled scalar offset, first half
            uint32_t af[2][4];
#pragma unroll
            for (int mi = 0; mi < 2; ++mi) {
                const uint32_t* p = Abase + mi * 16 * 32;
                af[mi][0] = p[x0];
                af[mi][1] = p[8 * 32 + x0];
                af[mi][2] = p[x0 ^ 4];
                af[mi][3] = p[8 * 32 + (x0 ^ 4)];
            }
#pragma unroll
            for (int ni = 0; ni < 8; ++ni) {
                const uint32_t* p = Bbase + ni * 8 * 32;
                uint32_t bf[2] = { p[x0], p[x0 ^ 4] };
                mma_tf32(acc[0][ni], af[0], bf);
                mma_tf32(acc[1][ni], af[1], bf);
            }
        }
    }

    // epilogue: direct float2 stores
#pragma unroll
    for (int mi = 0; mi < 2; ++mi) {
        const int row = bm + wm * 32 + mi * 16 + g;
#pragma unroll
        for (int ni = 0; ni < 8; ++ni) {
            const int col = bn + wn * 64 + ni * 8 + t4 * 2;
            *reinterpret_cast<float2*>(C + (size_t)row * GN + col) =
                make_float2(acc[mi][ni][0], acc[mi][ni][1]);
            *reinterpret_cast<float2*>(C + (size_t)(row + 8) * GN + col) =
                make_float2(acc[mi][ni][2], acc[mi][ni][3]);
        }
    }
}

// ---------------------------------------------------------------------------
// Fast tanh: 1 - 2/(exp(2z)+1).  Two MUFU ops (~45 cyc) vs libdevice tanhf
// (~60-80).  Saturates correctly for |z| large (exp->inf => 1, exp->0 => -1).
// Abs error ~1e-7 near 0 (cancellation) — negligible vs 4e-4 tf32 GEMM error.
// ---------------------------------------------------------------------------
__device__ __forceinline__ float fast_tanh(float z) {
    float ez = __expf(z + z);
    return 1.0f - __fdividef(2.0f, ez + 1.0f);
}

// ---------------------------------------------------------------------------
// Recurrent scan: one block per (b,h).  128 threads: thread t handles output
// element e = t>>1, k-half = t&1 (32 MACs each).
//   * x prefetch ring of DEPTH 8 (registers, outer loop unrolled x8):
//     8 outstanding DRAM loads per thread -> ~780cyc latency fully hidden
//     (R12's distance-2 prefetch left the scan latency-bound at ~780 cyc/step).
//   * 8 accumulators x 4-FMA chains + tree reduce: dep depth 28 vs 40.
//   * fast_tanh instead of tanhf.
//   * one bar.sync per step (double-buffered h state in smem).
// ---------------------------------------------------------------------------
__global__ void __launch_bounds__(128) rnn_scan(
    const float* __restrict__ xp, const float* __restrict__ h0,
    const float* __restrict__ Wst, const float* __restrict__ bias,
    float* __restrict__ y)
{
    const int b    = blockIdx.x >> 4;
    const int h    = blockIdx.x & 15;
    const int t    = threadIdx.x;
    const int e    = t >> 1;
    const int half = t & 1;

    __shared__ __align__(16) float hs[2][64];

    // per-thread weight slice: W[h][e][half*32 .. half*32+31]
    float w[32];
    {
        const float4* wr = reinterpret_cast<const float4*>(
            Wst + ((size_t)(h * 64 + e)) * 64 + half * 32);
#pragma unroll
        for (int c = 0; c < 8; ++c) {
            float4 v = wr[c];
            w[4 * c + 0] = v.x; w[4 * c + 1] = v.y;
            w[4 * c + 2] = v.z; w[4 * c + 3] = v.w;
        }
    }
    const float be = bias[h * 64 + e];

    if (t < 64) hs[0][t] = h0[(size_t)(b * HH + h) * 64 + t];

    const float* xb = xp + (size_t)b * SS * 1024 + h * 64 + e;
    float*       yb = y  + (size_t)b * SS * 1024 + h * 64 + e;

    // fill the depth-8 prefetch ring
    float xr[8];
#pragma unroll
    for (int i = 0; i < 8; ++i) xr[i] = xb[(size_t)i * 1024];
    const float* xnext = xb + (size_t)8 * 1024;   // xnext[st*1024] == xb[(st+8)*1024]

    __syncthreads();

    int cur = 0;
    for (int s = 0; s < SS; s += 8) {
#pragma unroll
        for (int i = 0; i < 8; ++i) {
            const int st = s + i;

            // issue next prefetch FIRST (independent of this step's compute)
            float xn = 0.f;
            if (st + 8 < SS) xn = xnext[(size_t)st * 1024];

            // matvec partial: 8 accumulators, 4 chained FMAs each
            const float4* hv = reinterpret_cast<const float4*>(&hs[cur][half * 32]);
            float a[8];
#pragma unroll
            for (int c = 0; c < 8; ++c) {
                float4 q = hv[c];
                a[c] = fmaf(w[4 * c + 0], q.x,
                        fmaf(w[4 * c + 1], q.y,
                         fmaf(w[4 * c + 2], q.z, w[4 * c + 3] * q.w)));
            }
            float acc = ((a[0] + a[1]) + (a[2] + a[3]))
                      + ((a[4] + a[5]) + (a[6] + a[7]));
            acc += __shfl_xor_sync(0xffffffffu, acc, 1);   // combine the two halves

            const float hn = fast_tanh(acc + be + xr[i]);

            if (half) yb[(size_t)st * 1024] = hn;   // lane 1 streams output
            else      hs[cur ^ 1][e] = hn;          // lane 0 updates state buffer
            __syncthreads();
            cur ^= 1;

            xr[i] = xn;   // ring slot i now holds x for step st+8
        }
    }
}

// ---------------------------------------------------------------------------
// Launch
// ---------------------------------------------------------------------------
extern "C" void kernel_launch(void* const* d_in, const int* in_sizes, int n_in,
                              void* d_out, int out_size)
{
    const float* x     = (const float*)d_in[0];  // [B,S,IN]
    const float* h0    = (const float*)d_in[1];  // [B,H,D]
    const float* w_in  = (const float*)d_in[2];  // [H*D, IN]
    const float* Wst   = (const float*)d_in[3];  // [H,D,D]
    const float* bias  = (const float*)d_in[4];  // [H,D]
    const float* w_out = (const float*)d_in[5];  // [OUT, H*D]
    float* out = (float*)d_out;                  // [B,S,OUT]

    float *xp = nullptr, *yy = nullptr;
    cudaGetSymbolAddress((void**)&xp, g_xp);
    cudaGetSymbolAddress((void**)&yy, g_y);

    dim3 grid(GN / 128, GM / 128);   // (8, 128)
    gemm_tf32<<<grid, 256>>>(x, w_in, xp);              // input projection
    rnn_scan<<<BB * HH, 128>>>(xp, h0, Wst, bias, yy);  // sequential recurrence
    gemm_tf32<<<grid, 256>>>(yy, w_out, out);           // output projection
}

// round 14
// speedup vs baseline: 2.1544x; 1.0055x over previous
#include <cuda_runtime.h>
#include <cstdint>
#include <cstddef>

// Problem constants
#define BB 4
#define SS 4096
#define HH 16
#define DD 64
#define GM 16384   // B*S
#define GN 1024    // H*D == OUT
#define GK 1024    // IN == H*D

// Intermediate buffers (allocation-free rule: device globals)
__device__ float g_xp[(size_t)GM * GN];  // input projection  [B,S,H*D]
__device__ float g_y [(size_t)GM * GN];  // scan outputs      [B,S,H*D]

// ---------------------------------------------------------------------------
// tf32 helpers
// ---------------------------------------------------------------------------
__device__ __forceinline__ uint32_t f2tf32(float f) {
    uint32_t u;
    asm("cvt.rna.tf32.f32 %0, %1;" : "=r"(u) : "f"(f));
    return u;
}

__device__ __forceinline__ void mma_tf32(float c[4], const uint32_t a[4], const uint32_t b[2]) {
    asm volatile(
        "mma.sync.aligned.m16n8k8.row.col.f32.tf32.tf32.f32 "
        "{%0,%1,%2,%3}, {%4,%5,%6,%7}, {%8,%9}, {%0,%1,%2,%3};"
        : "+f"(c[0]), "+f"(c[1]), "+f"(c[2]), "+f"(c[3])
        : "r"(a[0]), "r"(a[1]), "r"(a[2]), "r"(a[3]), "r"(b[0]), "r"(b[1]));
}

// ---------------------------------------------------------------------------
// GEMM: C[M,N] = A[M,K] * B[N,K]^T   (unchanged — 265us each)
// ---------------------------------------------------------------------------
__global__ __launch_bounds__(256) void gemm_tf32(
    const float* __restrict__ A, const float* __restrict__ B, float* __restrict__ C)
{
    __shared__ uint4 As4[128 * 8];
    __shared__ uint4 Bs4[128 * 8];

    const int tid  = threadIdx.x;
    const int warp = tid >> 5;
    const int lane = tid & 31;
    const int wm   = warp >> 1;      // 0..3
    const int wn   = warp & 1;       // 0..1
    const int g    = lane >> 2;      // group 0..7
    const int t4   = lane & 3;       // thread-in-group
    const int lr   = tid >> 3;       // staging row 0..31
    const int lc4  = tid & 7;        // staging float4 col 0..7
    const int bm   = blockIdx.y * 128;
    const int bn   = blockIdx.x * 128;

    const float4* Ag = reinterpret_cast<const float4*>(A) + (size_t)(bm + lr) * (GK / 4) + lc4;
    const float4* Bg = reinterpret_cast<const float4*>(B) + (size_t)(bn + lr) * (GK / 4) + lc4;
    const int sw = lc4 ^ (lr & 7);

    float acc[2][8][4];
#pragma unroll
    for (int mi = 0; mi < 2; ++mi)
#pragma unroll
        for (int ni = 0; ni < 8; ++ni)
#pragma unroll
            for (int r = 0; r < 4; ++r) acc[mi][ni][r] = 0.f;

    // prologue: stage K-tile 0
    float4 pa[4], pb[4];
#pragma unroll
    for (int i = 0; i < 4; ++i) {
        pa[i] = Ag[(size_t)i * 32 * (GK / 4)];
        pb[i] = Bg[(size_t)i * 32 * (GK / 4)];
    }

    const uint32_t* As = reinterpret_cast<const uint32_t*>(As4);
    const uint32_t* Bs = reinterpret_cast<const uint32_t*>(Bs4);
    const uint32_t* Abase = As + (wm * 32 + g) * 32 + t4;
    const uint32_t* Bbase = Bs + (wn * 64 + g) * 32 + t4;

    for (int kt = 0; kt < GK / 32; ++kt) {
        __syncthreads();   // previous compute finished reading smem
#pragma unroll
        for (int i = 0; i < 4; ++i) {
            As4[(lr + 32 * i) * 8 + sw] =
                make_uint4(f2tf32(pa[i].x), f2tf32(pa[i].y), f2tf32(pa[i].z), f2tf32(pa[i].w));
            Bs4[(lr + 32 * i) * 8 + sw] =
                make_uint4(f2tf32(pb[i].x), f2tf32(pb[i].y), f2tf32(pb[i].z), f2tf32(pb[i].w));
        }
        __syncthreads();   // smem tile ready

        if (kt + 1 < GK / 32) {        // prefetch next tile (overlaps compute)
#pragma unroll
            for (int i = 0; i < 4; ++i) {
                pa[i] = Ag[(size_t)(kt + 1) * 8 + (size_t)i * 32 * (GK / 4)];
                pb[i] = Bg[(size_t)(kt + 1) * 8 + (size_t)i * 32 * (GK / 4)];
            }
        }

#pragma unroll
        for (int j = 0; j < 4; ++j) {          // 4 k8-steps per K-tile
            const int x0 = ((2 * j) ^ g) * 4;  // swizzled scalar offset, first half
            uint32_t af[2][4];
#pragma unroll
            for (int mi = 0; mi < 2; ++mi) {
                const uint32_t* p = Abase + mi * 16 * 32;
                af[mi][0] = p[x0];
                af[mi][1] = p[8 * 32 + x0];
                af[mi][2] = p[x0 ^ 4];
                af[mi][3] = p[8 * 32 + (x0 ^ 4)];
            }
#pragma unroll
            for (int ni = 0; ni < 8; ++ni) {
                const uint32_t* p = Bbase + ni * 8 * 32;
                uint32_t bf[2] = { p[x0], p[x0 ^ 4] };
                mma_tf32(acc[0][ni], af[0], bf);
                mma_tf32(acc[1][ni], af[1], bf);
            }
        }
    }

    // epilogue: direct float2 stores
#pragma unroll
    for (int mi = 0; mi < 2; ++mi) {
        const int row = bm + wm * 32 + mi * 16 + g;
#pragma unroll
        for (int ni = 0; ni < 8; ++ni) {
            const int col = bn + wn * 64 + ni * 8 + t4 * 2;
            *reinterpret_cast<float2*>(C + (size_t)row * GN + col) =
                make_float2(acc[mi][ni][0], acc[mi][ni][1]);
            *reinterpret_cast<float2*>(C + (size_t)(row + 8) * GN + col) =
                make_float2(acc[mi][ni][2], acc[mi][ni][3]);
        }
    }
}

// ---------------------------------------------------------------------------
// packed f32x2 helpers (sm_103a FFMA2 — only reachable via PTX)
// ---------------------------------------------------------------------------
__device__ __forceinline__ void ffma2(uint64_t& c, uint64_t a, uint64_t b) {
    asm("fma.rn.f32x2 %0, %1, %2, %0;" : "+l"(c) : "l"(a), "l"(b));
}
__device__ __forceinline__ void fadd2(uint64_t& c, uint64_t a) {
    asm("add.rn.f32x2 %0, %0, %1;" : "+l"(c) : "l"(a));
}
__device__ __forceinline__ float2 unpk(uint64_t v) {
    float2 r;
    asm("mov.b64 {%0,%1}, %2;" : "=f"(r.x), "=f"(r.y) : "l"(v));
    return r;
}

// fast tanh: 1 - 2/(exp(2z)+1).  ~45cyc, correct saturation, ~1e-7 error.
__device__ __forceinline__ float fast_tanh(float z) {
    float ez = __expf(z + z);
    return 1.0f - __fdividef(2.0f, ez + 1.0f);
}

// ---------------------------------------------------------------------------
// Warp-synchronous scan: ONE WARP per (b,h) — no bar.sync anywhere.
// Thread t owns the contiguous element pair (2t, 2t+1):
//   * weights for both rows in registers as packed f32x2 (64 x u64)
//   * h state double-buffered in smem, read via broadcast LDS.128,
//     written as one STS.64, made visible by __syncwarp (~23cyc vs BAR ~47+)
//   * 64 FFMA2 (depth-8 chains) + 3 packed adds per element: ~110 issue/step
//   * x prefetch ring depth 8 (float2), y streamed as STG.64
// ---------------------------------------------------------------------------
__global__ void __launch_bounds__(32) rnn_scan(
    const float* __restrict__ xp, const float* __restrict__ h0,
    const float* __restrict__ Wst, const float* __restrict__ bias,
    float* __restrict__ y)
{
    const int b  = blockIdx.x >> 4;
    const int h  = blockIdx.x & 15;
    const int t  = threadIdx.x;
    const int e0 = 2 * t;            // elements e0, e0+1

    __shared__ __align__(16) float hs[2][64];

    // weight rows e0, e0+1 as packed k-pairs: w[row][p] = (W[e][2p], W[e][2p+1])
    uint64_t w0[32], w1[32];
    {
        const uint64_t* p0 = reinterpret_cast<const uint64_t*>(
            Wst + ((size_t)(h * 64 + e0)) * 64);
        const uint64_t* p1 = p0 + 32;
#pragma unroll
        for (int k = 0; k < 32; ++k) { w0[k] = p0[k]; w1[k] = p1[k]; }
    }
    const float2 be = *reinterpret_cast<const float2*>(bias + h * 64 + e0);

    // init state
    reinterpret_cast<float2*>(hs[0])[t] =
        reinterpret_cast<const float2*>(h0 + (size_t)(b * HH + h) * 64)[t];

    const float2* xb2 = reinterpret_cast<const float2*>(
        xp + (size_t)b * SS * 1024 + h * 64) + t;      // step stride = 512 float2
    float2* yb2 = reinterpret_cast<float2*>(
        y + (size_t)b * SS * 1024 + h * 64) + t;

    // depth-8 prefetch ring
    float2 xr[8];
#pragma unroll
    for (int i = 0; i < 8; ++i) xr[i] = xb2[(size_t)i * 512];

    __syncwarp();

    int cur = 0;
    for (int s = 0; s < SS; s += 8) {
#pragma unroll
        for (int i = 0; i < 8; ++i) {
            const int st = s + i;

            // issue next prefetch first (independent)
            float2 xn = make_float2(0.f, 0.f);
            if (st + 8 < SS) xn = xb2[(size_t)(st + 8) * 512];

            // dual dot-product: 64 FFMA2, 4 accs each (depth 8)
            const ulonglong2* hv = reinterpret_cast<const ulonglong2*>(hs[cur]);
            uint64_t a0[4] = {0, 0, 0, 0}, a1[4] = {0, 0, 0, 0};
#pragma unroll
            for (int k = 0; k < 16; ++k) {
                ulonglong2 q = hv[k];                      // broadcast LDS.128
                ffma2(a0[(2 * k) & 3],     w0[2 * k],     q.x);
                ffma2(a0[(2 * k + 1) & 3], w0[2 * k + 1], q.y);
                ffma2(a1[(2 * k) & 3],     w1[2 * k],     q.x);
                ffma2(a1[(2 * k + 1) & 3], w1[2 * k + 1], q.y);
            }
            fadd2(a0[0], a0[1]); fadd2(a0[2], a0[3]); fadd2(a0[0], a0[2]);
            fadd2(a1[0], a1[1]); fadd2(a1[2], a1[3]); fadd2(a1[0], a1[2]);
            float2 s0 = unpk(a0[0]);
            float2 s1 = unpk(a1[0]);

            const float hn0 = fast_tanh((s0.x + s0.y) + be.x + xr[i].x);
            const float hn1 = fast_tanh((s1.x + s1.y) + be.y + xr[i].y);
            const float2 hn = make_float2(hn0, hn1);

            yb2[(size_t)st * 512] = hn;                              // STG.64
            *reinterpret_cast<float2*>(&hs[cur ^ 1][e0]) = hn;       // STS.64
            __syncwarp();
            cur ^= 1;

            xr[i] = xn;
        }
    }
}

// ---------------------------------------------------------------------------
// Launch
// ---------------------------------------------------------------------------
extern "C" void kernel_launch(void* const* d_in, const int* in_sizes, int n_in,
                              void* d_out, int out_size)
{
    const float* x     = (const float*)d_in[0];  // [B,S,IN]
    const float* h0    = (const float*)d_in[1];  // [B,H,D]
    const float* w_in  = (const float*)d_in[2];  // [H*D, IN]
    const float* Wst   = (const float*)d_in[3];  // [H,D,D]
    const float* bias  = (const float*)d_in[4];  // [H,D]
    const float* w_out = (const float*)d_in[5];  // [OUT, H*D]
    float* out = (float*)d_out;                  // [B,S,OUT]

    float *xp = nullptr, *yy = nullptr;
    cudaGetSymbolAddress((void**)&xp, g_xp);
    cudaGetSymbolAddress((void**)&yy, g_y);

    dim3 grid(GN / 128, GM / 128);   // (8, 128)
    gemm_tf32<<<grid, 256>>>(x, w_in, xp);              // input projection
    rnn_scan<<<BB * HH, 32>>>(xp, h0, Wst, bias, yy);   // sequential recurrence
    gemm_tf32<<<grid, 256>>>(yy, w_out, out);           // output projection
}